// round 11
// baseline (speedup 1.0000x reference)
#include <cuda_runtime.h>
#include <cuda_fp16.h>
#include <math.h>
#include <stdint.h>

typedef long long TLL;
typedef __half f16;

// ---------------- problem constants ----------------
#define BB   4
#define TT   2048
#define CC   1024
#define HH   16
#define HD   64
#define DFF  4096
#define ROWS (BB*TT)          // 8192

// ---------------- scratch ----------------
__device__ float g_x1  [(TLL)ROWS*CC];          // residual 1 (fp32)

__device__ f16 g_h_hi [(TLL)ROWS*CC];
__device__ f16 g_qkv_hi[(TLL)ROWS*3*CC];
__device__ f16 g_y_hi [(TLL)ROWS*CC];
__device__ f16 g_h2_hi[(TLL)ROWS*CC],      g_h2_lo[(TLL)ROWS*CC];
__device__ f16 g_ff_hi[(TLL)ROWS*DFF],     g_ff_lo[(TLL)ROWS*DFF];
__device__ f16 g_wqkvT_hi[(TLL)3*CC*CC];
__device__ f16 g_wapT_hi [(TLL)CC*CC];
__device__ f16 g_wfcT_hi [(TLL)DFF*CC];
__device__ f16 g_wprjT_hi[(TLL)CC*DFF];

// ---------------- helpers ----------------
__device__ __forceinline__ uint32_t smem_u32(const void* p) {
    return (uint32_t)__cvta_generic_to_shared(p);
}
__device__ __forceinline__ float tanh_ap(float x) {
    float y; asm("tanh.approx.f32 %0, %1;" : "=f"(y) : "f"(x)); return y;
}
__device__ __forceinline__ float gelu_f(float x) {
    const float c = 0.7978845608028654f;
    float t = tanh_ap(c * (x + 0.044715f * x * x * x));
    return 0.5f * x * (1.0f + t);
}
__device__ __forceinline__ float ex2f(float x) {
    float y; asm("ex2.approx.f32 %0, %1;" : "=f"(y) : "f"(x)); return y;
}
__device__ __forceinline__ void split_h(float v, f16& h, f16& l) {
    h = __float2half_rn(v);
    l = __float2half_rn(v - __half2float(h));
}
__device__ __forceinline__ void mma_f16(float* d, const uint32_t* a, const uint32_t* b) {
    asm volatile(
        "mma.sync.aligned.m16n8k16.row.col.f32.f16.f16.f32 "
        "{%0,%1,%2,%3}, {%4,%5,%6,%7}, {%8,%9}, {%0,%1,%2,%3};"
        : "+f"(d[0]), "+f"(d[1]), "+f"(d[2]), "+f"(d[3])
        : "r"(a[0]), "r"(a[1]), "r"(a[2]), "r"(a[3]), "r"(b[0]), "r"(b[1]));
}
#define LDSM4(r, addr) \
    asm volatile("ldmatrix.sync.aligned.m8n8.x4.shared.b16 {%0,%1,%2,%3}, [%4];" \
        : "=r"((r)[0]), "=r"((r)[1]), "=r"((r)[2]), "=r"((r)[3]) : "r"(addr))
#define LDSM4T(r, addr) \
    asm volatile("ldmatrix.sync.aligned.m8n8.x4.trans.shared.b16 {%0,%1,%2,%3}, [%4];" \
        : "=r"((r)[0]), "=r"((r)[1]), "=r"((r)[2]), "=r"((r)[3]) : "r"(addr))
#define CP16(dst, src) \
    asm volatile("cp.async.cg.shared.global [%0], [%1], 16;" :: "r"(dst), "l"(src))

// ---------------- LayerNorm variants ----------------
template <bool DUAL>
__global__ void ln_kernel(const float* __restrict__ x,
                          const float* __restrict__ g,
                          const float* __restrict__ b,
                          f16* __restrict__ oh, f16* __restrict__ ol) {
    const int row = blockIdx.x;
    const float* xr = x + (TLL)row * CC;
    float v[4]; float s = 0.f, ss = 0.f;
#pragma unroll
    for (int i = 0; i < 4; i++) {
        v[i] = xr[threadIdx.x + 256 * i];
        s += v[i]; ss += v[i] * v[i];
    }
#pragma unroll
    for (int o = 16; o; o >>= 1) {
        s  += __shfl_xor_sync(0xffffffffu, s, o);
        ss += __shfl_xor_sync(0xffffffffu, ss, o);
    }
    __shared__ float sh0[8], sh1[8];
    int w = threadIdx.x >> 5, l = threadIdx.x & 31;
    if (!l) { sh0[w] = s; sh1[w] = ss; }
    __syncthreads();
    if (threadIdx.x == 0) {
        float S = 0.f, SS = 0.f;
#pragma unroll
        for (int i = 0; i < 8; i++) { S += sh0[i]; SS += sh1[i]; }
        float mu = S * (1.0f / CC);
        float var = SS * (1.0f / CC) - mu * mu;
        sh0[0] = mu; sh1[0] = rsqrtf(var + 1e-5f);
    }
    __syncthreads();
    float mu = sh0[0], rstd = sh1[0];
#pragma unroll
    for (int i = 0; i < 4; i++) {
        int c = threadIdx.x + 256 * i;
        float o = (v[i] - mu) * rstd * g[c] + b[c];
        if (DUAL) {
            f16 hi, lo; split_h(o, hi, lo);
            oh[(TLL)row * CC + c] = hi;
            ol[(TLL)row * CC + c] = lo;
        } else {
            oh[(TLL)row * CC + c] = __float2half_rn(o);
        }
    }
}

// ---------------- transpose fp32 -> fp16 hi ([K,N] -> [N,K]) ---------------
__global__ void transpose_conv(const float* __restrict__ in,
                               f16* __restrict__ oh, int ldin, int ldout) {
    __shared__ float t[32][33];
    int k0 = blockIdx.y * 32, n0 = blockIdx.x * 32;
    int tx = threadIdx.x, ty = threadIdx.y;
#pragma unroll
    for (int i = 0; i < 32; i += 8)
        t[ty + i][tx] = in[(TLL)(k0 + ty + i) * ldin + (n0 + tx)];
    __syncthreads();
#pragma unroll
    for (int i = 0; i < 32; i += 8)
        oh[(TLL)(n0 + ty + i) * ldout + (k0 + tx)] = __float2half_rn(t[tx][ty + i]);
}

// ---------------- fused flash attention -----------------------------------
// grid (16, 1, 64): z = b*16 + h, x = 128-row Q block. 256 threads, 8 warps,
// each warp owns 16 Q rows. K/V tiles 128x64, double buffered. y out: f16 hi.
__global__ void __launch_bounds__(256)
flash_attn(const f16* __restrict__ qkv, f16* __restrict__ yh) {
    constexpr int RS = 72;                     // f16 per smem row
    constexpr int TILE = 128 * RS * 2;         // bytes per 128x64 tile
    extern __shared__ __align__(16) f16 fsm[];
    const uint32_t sQ  = smem_u32(fsm);
    const uint32_t sKV = sQ + TILE;

    const int tid = threadIdx.x, lane = tid & 31, wid = tid >> 5;
    const int lq = lane >> 2, lr = lane & 3;
    const int z = blockIdx.z, bz = z >> 4, hz = z & 15;
    const int t0 = blockIdx.x * 128;

    const f16* Qg = qkv + ((TLL)bz * TT + t0) * (3 * CC) + hz * HD;
    const f16* Kg = qkv + ((TLL)bz * TT) * (3 * CC) + CC + hz * HD;
    const f16* Vg = Kg + CC;

#pragma unroll
    for (int t = 0; t < 4; t++) {
        int idx = tid + (t << 8);
        int r = idx >> 3, c = idx & 7;
        CP16(sQ + (r * RS + c * 8) * 2, Qg + (TLL)r * (3 * CC) + c * 8);
    }
    asm volatile("cp.async.commit_group;");

    auto stageKV = [&](int buf, int s0) {
        uint32_t base = sKV + buf * (2 * TILE);
#pragma unroll
        for (int t = 0; t < 4; t++) {
            int idx = tid + (t << 8);
            int r = idx >> 3, c = idx & 7;
            CP16(base + (r * RS + c * 8) * 2, Kg + (TLL)(s0 + r) * (3 * CC) + c * 8);
            CP16(base + TILE + (r * RS + c * 8) * 2, Vg + (TLL)(s0 + r) * (3 * CC) + c * 8);
        }
        asm volatile("cp.async.commit_group;");
    };
    stageKV(0, 0);

    uint32_t qf[4][4];
    float y[8][4];
    float m_lo = -1e30f, m_hi = -1e30f, l_lo = 0.f, l_hi = 0.f;
#pragma unroll
    for (int i = 0; i < 8; i++)
#pragma unroll
        for (int q = 0; q < 4; q++) y[i][q] = 0.f;

    const float c_s = 0.125f * 1.4426950408889634f;

    for (int it = 0; it < TT / 128; ++it) {
        if (it + 1 < TT / 128) {
            stageKV((it + 1) & 1, (it + 1) * 128);
            asm volatile("cp.async.wait_group 1;" ::: "memory");
        } else {
            asm volatile("cp.async.wait_group 0;" ::: "memory");
        }
        __syncthreads();

        if (it == 0) {
#pragma unroll
            for (int c = 0; c < 4; c++) {
                uint32_t a = sQ + (((wid * 16) + (lane & 15)) * RS
                                   + c * 16 + ((lane >> 4) & 1) * 8) * 2;
                LDSM4(qf[c], a);
            }
        }

        const uint32_t bbK = sKV + (it & 1) * (2 * TILE);
        const uint32_t bbV = bbK + TILE;

        float S[16][4];
#pragma unroll
        for (int nt = 0; nt < 16; nt++) {
            S[nt][0] = S[nt][1] = S[nt][2] = S[nt][3] = 0.f;
            uint32_t b0[4], b1[4];
            uint32_t a0 = bbK + ((nt * 8 + (lane & 7)) * RS + ((lane >> 3) & 3) * 8) * 2;
            LDSM4(b0, a0);
            LDSM4(b1, a0 + 64);
            mma_f16(S[nt], qf[0], b0);
            mma_f16(S[nt], qf[1], b0 + 2);
            mma_f16(S[nt], qf[2], b1);
            mma_f16(S[nt], qf[3], b1 + 2);
        }

        float mx0 = -1e30f, mx1 = -1e30f;
#pragma unroll
        for (int nt = 0; nt < 16; nt++) {
            S[nt][0] *= c_s; S[nt][1] *= c_s; S[nt][2] *= c_s; S[nt][3] *= c_s;
            mx0 = fmaxf(mx0, fmaxf(S[nt][0], S[nt][1]));
            mx1 = fmaxf(mx1, fmaxf(S[nt][2], S[nt][3]));
        }
        mx0 = fmaxf(mx0, __shfl_xor_sync(0xffffffffu, mx0, 1));
        mx0 = fmaxf(mx0, __shfl_xor_sync(0xffffffffu, mx0, 2));
        mx1 = fmaxf(mx1, __shfl_xor_sync(0xffffffffu, mx1, 1));
        mx1 = fmaxf(mx1, __shfl_xor_sync(0xffffffffu, mx1, 2));
        float nmlo = fmaxf(m_lo, mx0), nmhi = fmaxf(m_hi, mx1);
        float al = ex2f(m_lo - nmlo), ah = ex2f(m_hi - nmhi);
        m_lo = nmlo; m_hi = nmhi;
        l_lo *= al; l_hi *= ah;
#pragma unroll
        for (int i = 0; i < 8; i++) {
            y[i][0] *= al; y[i][1] *= al; y[i][2] *= ah; y[i][3] *= ah;
        }

        uint32_t pa[8][4];
#pragma unroll
        for (int kc = 0; kc < 8; kc++) {
#pragma unroll
            for (int half = 0; half < 2; half++) {
                int nt = 2 * kc + half;
                float p0 = ex2f(S[nt][0] - m_lo);
                float p1 = ex2f(S[nt][1] - m_lo);
                float p2 = ex2f(S[nt][2] - m_hi);
                float p3 = ex2f(S[nt][3] - m_hi);
                l_lo += p0 + p1; l_hi += p2 + p3;
                __half2 q01 = __floats2half2_rn(p0, p1);
                __half2 q23 = __floats2half2_rn(p2, p3);
                pa[kc][2 * half + 0] = *(uint32_t*)&q01;
                pa[kc][2 * half + 1] = *(uint32_t*)&q23;
            }
        }

#pragma unroll
        for (int kc = 0; kc < 8; kc++) {
#pragma unroll
            for (int np = 0; np < 4; np++) {
                uint32_t vf[4];
                uint32_t a = bbV + ((kc * 16 + ((lane >> 3) & 1) * 8 + (lane & 7)) * RS
                                    + np * 16 + ((lane >> 4) & 1) * 8) * 2;
                LDSM4T(vf, a);
                mma_f16(y[2 * np], pa[kc], vf);
                mma_f16(y[2 * np + 1], pa[kc], vf + 2);
            }
        }
        __syncthreads();
    }

    l_lo += __shfl_xor_sync(0xffffffffu, l_lo, 1);
    l_lo += __shfl_xor_sync(0xffffffffu, l_lo, 2);
    l_hi += __shfl_xor_sync(0xffffffffu, l_hi, 1);
    l_hi += __shfl_xor_sync(0xffffffffu, l_hi, 2);
    float inv_lo = 1.f / l_lo, inv_hi = 1.f / l_hi;

    TLL row_lo = (TLL)bz * TT + t0 + wid * 16 + lq;
    TLL row_hi = row_lo + 8;
#pragma unroll
    for (int nt = 0; nt < 8; nt++) {
        int col = hz * HD + nt * 8 + 2 * lr;
        __half2 p0 = __floats2half2_rn(y[nt][0] * inv_lo, y[nt][1] * inv_lo);
        __half2 p1 = __floats2half2_rn(y[nt][2] * inv_hi, y[nt][3] * inv_hi);
        *(__half2*)(yh + row_lo * CC + col) = p0;
        *(__half2*)(yh + row_hi * CC + col) = p1;
    }
}

// ---------------- fp16 mma.sync GEMM, 128x256 tile, 3-stage ----------------
// D[m][n] = scale * sum_k A[m][k]*B[n][k], K-major operands.
// SPLITA: A = Ah + Al (2 MMAs: Al*Bh + Ah*Bh). B always hi-only fp16.
// CTA tile 128x256, BK=32, 256 threads, warp grid 2(m) x 4(n), warp tile 64x64.
// 3-stage cp.async pipeline, ONE __syncthreads per iteration.
// flags: 1=+bias, 2=gelu, 4=+residual(fp32), 8=dual f16 out, 16=hi-only f16 out
template <bool SPLITA>
__global__ void __launch_bounds__(256, 1)
hf_gemm(const f16* __restrict__ Ah, const f16* __restrict__ Al,
        const f16* __restrict__ Bh,
        const float* __restrict__ bias, const float* __restrict__ res,
        float* __restrict__ Cf, f16* __restrict__ Oh, f16* __restrict__ Ol,
        int K, TLL lda, TLL ldb, TLL ldc,
        float scale, int flags) {
    constexpr int BN = 256;
    constexpr int RS = 40;
    constexpr int NA = SPLITA ? 2 : 1;
    constexpr int A_ELEMS = 128 * RS;
    constexpr int B_ELEMS = BN * RS;
    constexpr int BUF = NA * A_ELEMS + B_ELEMS;

    extern __shared__ __align__(16) f16 dynsm[];
    const uint32_t sb = smem_u32(dynsm);

    const int tid = threadIdx.x, lane = tid & 31, wid = tid >> 5;
    const int wm = wid & 1, wn = wid >> 1;    // 2 x 4 warp grid, warp tile 64x64

    const TLL rowBase = (TLL)blockIdx.y * 128;
    const TLL colBase = (TLL)blockIdx.x * BN;

    float acc[4][8][4];
#pragma unroll
    for (int i = 0; i < 4; i++)
#pragma unroll
        for (int j = 0; j < 8; j++)
#pragma unroll
            for (int q = 0; q < 4; q++) acc[i][j][q] = 0.f;

    auto stage = [&](int s, int k0) {
        const uint32_t bb = sb + (s % 3) * (BUF * 2);
#pragma unroll
        for (int t = 0; t < 2 * NA; t++) {          // A: NA arrays x 512 chunks
            int idx = tid + (t << 8);
            int arr = idx >> 9, i2 = idx & 511;
            int r = i2 >> 2, c = i2 & 3;
            const f16* g = (arr ? Al : Ah) + (rowBase + r) * lda + (k0 + c * 8);
            uint32_t d = bb + (arr * A_ELEMS + r * RS + c * 8) * 2;
            CP16(d, g);
        }
#pragma unroll
        for (int t = 0; t < 4; t++) {               // B: 256 rows x 4 chunks
            int idx = tid + (t << 8);
            int r = idx >> 2, c = idx & 3;
            const f16* g = Bh + (colBase + r) * ldb + (k0 + c * 8);
            uint32_t d = bb + (NA * A_ELEMS + r * RS + c * 8) * 2;
            CP16(d, g);
        }
        asm volatile("cp.async.commit_group;");
    };

    const int iters = K / 32;
    stage(0, 0);
    if (iters > 1) stage(1, 32);

    const uint32_t aRow = (wm * 64 + (lane & 15)) * (RS * 2) + ((lane >> 4) << 4);
    const uint32_t bRow4 = (wn * 64 + ((lane >> 4) & 1) * 8 + (lane & 7)) * (RS * 2)
                         + (((lane >> 3) & 1) << 4);

    for (int it = 0; it < iters; ++it) {
        if (it + 1 < iters) {
            asm volatile("cp.async.wait_group 1;" ::: "memory");
        } else {
            asm volatile("cp.async.wait_group 0;" ::: "memory");
        }
        __syncthreads();
        if (it + 2 < iters) stage(it + 2, (it + 2) * 32);

        const uint32_t bb = sb + (it % 3) * (BUF * 2);

#pragma unroll
        for (int ks = 0; ks < 2; ks++) {
            uint32_t bq[4][4];
#pragma unroll
            for (int p = 0; p < 4; p++) {
                uint32_t ba = bb + NA * A_ELEMS * 2 + bRow4 + p * (16 * RS * 2) + ks * 32;
                LDSM4(bq[p], ba);
            }
#pragma unroll
            for (int mi = 0; mi < 4; mi++) {
                uint32_t aa = bb + aRow + mi * (16 * RS * 2) + ks * 32;
                uint32_t ah[4], al[4];
                LDSM4(ah, aa);
                if (SPLITA) LDSM4(al, aa + A_ELEMS * 2);
#pragma unroll
                for (int p = 0; p < 4; p++) {
                    if (SPLITA) {
                        mma_f16(acc[mi][2 * p],     al, &bq[p][0]);
                        mma_f16(acc[mi][2 * p + 1], al, &bq[p][2]);
                    }
                    mma_f16(acc[mi][2 * p],     ah, &bq[p][0]);
                    mma_f16(acc[mi][2 * p + 1], ah, &bq[p][2]);
                }
            }
        }
    }

    const int lq = lane >> 2, lr = lane & 3;
#pragma unroll
    for (int mi = 0; mi < 4; mi++) {
        TLL r0 = rowBase + wm * 64 + mi * 16 + lq;
#pragma unroll
        for (int ni = 0; ni < 8; ni++) {
            TLL c = colBase + wn * 64 + ni * 8 + 2 * lr;
            float v00 = acc[mi][ni][0] * scale, v01 = acc[mi][ni][1] * scale;
            float v10 = acc[mi][ni][2] * scale, v11 = acc[mi][ni][3] * scale;
            if (flags & 1) {
                float b0 = bias[c], b1 = bias[c + 1];
                v00 += b0; v01 += b1; v10 += b0; v11 += b1;
            }
            if (flags & 2) {
                v00 = gelu_f(v00); v01 = gelu_f(v01);
                v10 = gelu_f(v10); v11 = gelu_f(v11);
            }
            if (flags & 4) {
                float2 ra = *(const float2*)(res + r0 * ldc + c);
                float2 rb = *(const float2*)(res + (r0 + 8) * ldc + c);
                v00 += ra.x; v01 += ra.y; v10 += rb.x; v11 += rb.y;
            }
            if (flags & 8) {
                f16 h0, l0, h1, l1;
                __half2 ph, pl;
                split_h(v00, h0, l0); split_h(v01, h1, l1);
                ph = __halves2half2(h0, h1); pl = __halves2half2(l0, l1);
                *(__half2*)(Oh + r0 * ldc + c) = ph;
                *(__half2*)(Ol + r0 * ldc + c) = pl;
                split_h(v10, h0, l0); split_h(v11, h1, l1);
                ph = __halves2half2(h0, h1); pl = __halves2half2(l0, l1);
                *(__half2*)(Oh + (r0 + 8) * ldc + c) = ph;
                *(__half2*)(Ol + (r0 + 8) * ldc + c) = pl;
            } else if (flags & 16) {
                *(__half2*)(Oh + r0 * ldc + c) = __floats2half2_rn(v00, v01);
                *(__half2*)(Oh + (r0 + 8) * ldc + c) = __floats2half2_rn(v10, v11);
            } else {
                *(float2*)(Cf + r0 * ldc + c) = make_float2(v00, v01);
                *(float2*)(Cf + (r0 + 8) * ldc + c) = make_float2(v10, v11);
            }
        }
    }
}

// ---------------- launch ----------------
extern "C" void kernel_launch(void* const* d_in, const int* in_sizes, int n_in,
                              void* d_out, int out_size) {
    const float* x          = (const float*)d_in[0];
    const float* ln1_g      = (const float*)d_in[1];
    const float* ln1_b      = (const float*)d_in[2];
    const float* w_qkv      = (const float*)d_in[3];
    const float* b_qkv      = (const float*)d_in[4];
    const float* w_attnproj = (const float*)d_in[5];
    const float* b_attnproj = (const float*)d_in[6];
    const float* ln2_g      = (const float*)d_in[7];
    const float* ln2_b      = (const float*)d_in[8];
    const float* w_fc       = (const float*)d_in[9];
    const float* b_fc       = (const float*)d_in[10];
    const float* w_proj     = (const float*)d_in[11];
    const float* b_proj     = (const float*)d_in[12];
    float* out = (float*)d_out;

    float *x1;
    f16 *h_hi, *qkv_hi, *y_hi, *h2_hi, *h2_lo, *ff_hi, *ff_lo;
    f16 *wqkvT_hi, *wapT_hi, *wfcT_hi, *wprjT_hi;
    cudaGetSymbolAddress((void**)&x1,   g_x1);
    cudaGetSymbolAddress((void**)&h_hi, g_h_hi);
    cudaGetSymbolAddress((void**)&qkv_hi, g_qkv_hi);
    cudaGetSymbolAddress((void**)&y_hi, g_y_hi);
    cudaGetSymbolAddress((void**)&h2_hi, g_h2_hi); cudaGetSymbolAddress((void**)&h2_lo, g_h2_lo);
    cudaGetSymbolAddress((void**)&ff_hi, g_ff_hi); cudaGetSymbolAddress((void**)&ff_lo, g_ff_lo);
    cudaGetSymbolAddress((void**)&wqkvT_hi, g_wqkvT_hi);
    cudaGetSymbolAddress((void**)&wapT_hi, g_wapT_hi);
    cudaGetSymbolAddress((void**)&wfcT_hi, g_wfcT_hi);
    cudaGetSymbolAddress((void**)&wprjT_hi, g_wprjT_hi);

    static bool attr_done = false;
    if (!attr_done) {
        cudaFuncSetAttribute(hf_gemm<true>,  cudaFuncAttributeMaxDynamicSharedMemorySize, 122880);
        cudaFuncSetAttribute(hf_gemm<false>, cudaFuncAttributeMaxDynamicSharedMemorySize, 92160);
        cudaFuncSetAttribute(flash_attn,     cudaFuncAttributeMaxDynamicSharedMemorySize, 92160);
        attr_done = true;
    }
    const int SM2 = 122880, SM1 = 92160, SMFA = 92160;

    dim3 tb(32, 8);
    transpose_conv<<<dim3(3 * CC / 32, CC / 32), tb>>>(w_qkv, wqkvT_hi, 3 * CC, CC);
    transpose_conv<<<dim3(CC / 32, CC / 32), tb>>>(w_attnproj, wapT_hi, CC, CC);
    transpose_conv<<<dim3(DFF / 32, CC / 32), tb>>>(w_fc, wfcT_hi, DFF, CC);
    transpose_conv<<<dim3(CC / 32, DFF / 32), tb>>>(w_proj, wprjT_hi, CC, DFF);

    // 1) h = LN1(x)  (hi only)
    ln_kernel<false><<<ROWS, 256>>>(x, ln1_g, ln1_b, h_hi, nullptr);

    // 2) qkv = h @ w_qkv + b_qkv  (plain fp16, hi out)  N=3072
    hf_gemm<false><<<dim3(3 * CC / 256, ROWS / 128, 1), 256, SM1>>>(
        h_hi, nullptr, wqkvT_hi, b_qkv, nullptr,
        nullptr, qkv_hi, nullptr, CC,
        CC, CC, 3 * CC, 1.0f, 1 | 16);

    // 3-6) fused attention: y = softmax(QK^T/8) V  (hi out)
    flash_attn<<<dim3(TT / 128, 1, BB * HH), 256, SMFA>>>(qkv_hi, y_hi);

    // 7) x1 = x + y @ w_attnproj + b  (plain fp16, fp32 out)  N=1024
    hf_gemm<false><<<dim3(CC / 256, ROWS / 128, 1), 256, SM1>>>(
        y_hi, nullptr, wapT_hi, b_attnproj, x,
        x1, nullptr, nullptr, CC,
        CC, CC, CC, 1.0f, 1 | 4);

    // 8) h2 = LN2(x1)  (dual fp16)
    ln_kernel<true><<<ROWS, 256>>>(x1, ln2_g, ln2_b, h2_hi, h2_lo);

    // 9) ff = gelu(h2 @ w_fc + b_fc)  (A-split x2, dual out)  N=4096
    hf_gemm<true><<<dim3(DFF / 256, ROWS / 128, 1), 256, SM2>>>(
        h2_hi, h2_lo, wfcT_hi, b_fc, nullptr,
        nullptr, ff_hi, ff_lo, CC,
        CC, CC, DFF, 1.0f, 1 | 2 | 8);

    // 10) out = x1 + ff @ w_proj + b_proj  (A-split x2, fp32 out)  N=1024, K=4096
    hf_gemm<true><<<dim3(CC / 256, ROWS / 128, 1), 256, SM2>>>(
        ff_hi, ff_lo, wprjT_hi, b_proj, x1,
        out, nullptr, nullptr, DFF,
        DFF, DFF, CC, 1.0f, 1 | 4);
}

// round 12
// speedup vs baseline: 1.3658x; 1.3658x over previous
#include <cuda_runtime.h>
#include <cuda_fp16.h>
#include <math.h>
#include <stdint.h>

typedef long long TLL;
typedef __half f16;

// ---------------- problem constants ----------------
#define BB   4
#define TT   2048
#define CC   1024
#define HH   16
#define HD   64
#define DFF  4096
#define ROWS (BB*TT)          // 8192

// ---------------- scratch ----------------
__device__ float g_x1  [(TLL)ROWS*CC];          // residual 1 (fp32)

__device__ f16 g_h_hi [(TLL)ROWS*CC];
__device__ f16 g_qkv_hi[(TLL)ROWS*3*CC];
__device__ f16 g_y_hi [(TLL)ROWS*CC];
__device__ f16 g_h2_hi[(TLL)ROWS*CC];
__device__ f16 g_ff_hi[(TLL)ROWS*DFF];
__device__ f16 g_wqkvT_hi[(TLL)3*CC*CC];
__device__ f16 g_wapT_hi [(TLL)CC*CC];
__device__ f16 g_wfcT_hi [(TLL)DFF*CC];
__device__ f16 g_wprjT_hi[(TLL)CC*DFF];

// ---------------- helpers ----------------
__device__ __forceinline__ uint32_t smem_u32(const void* p) {
    return (uint32_t)__cvta_generic_to_shared(p);
}
__device__ __forceinline__ float tanh_ap(float x) {
    float y; asm("tanh.approx.f32 %0, %1;" : "=f"(y) : "f"(x)); return y;
}
__device__ __forceinline__ float gelu_f(float x) {
    const float c = 0.7978845608028654f;
    float t = tanh_ap(c * (x + 0.044715f * x * x * x));
    return 0.5f * x * (1.0f + t);
}
__device__ __forceinline__ float ex2f(float x) {
    float y; asm("ex2.approx.f32 %0, %1;" : "=f"(y) : "f"(x)); return y;
}
__device__ __forceinline__ void mma_f16(float* d, const uint32_t* a, const uint32_t* b) {
    asm volatile(
        "mma.sync.aligned.m16n8k16.row.col.f32.f16.f16.f32 "
        "{%0,%1,%2,%3}, {%4,%5,%6,%7}, {%8,%9}, {%0,%1,%2,%3};"
        : "+f"(d[0]), "+f"(d[1]), "+f"(d[2]), "+f"(d[3])
        : "r"(a[0]), "r"(a[1]), "r"(a[2]), "r"(a[3]), "r"(b[0]), "r"(b[1]));
}
#define LDSM4(r, addr) \
    asm volatile("ldmatrix.sync.aligned.m8n8.x4.shared.b16 {%0,%1,%2,%3}, [%4];" \
        : "=r"((r)[0]), "=r"((r)[1]), "=r"((r)[2]), "=r"((r)[3]) : "r"(addr))
#define LDSM4T(r, addr) \
    asm volatile("ldmatrix.sync.aligned.m8n8.x4.trans.shared.b16 {%0,%1,%2,%3}, [%4];" \
        : "=r"((r)[0]), "=r"((r)[1]), "=r"((r)[2]), "=r"((r)[3]) : "r"(addr))
#define LDSM2(r, addr) \
    asm volatile("ldmatrix.sync.aligned.m8n8.x2.shared.b16 {%0,%1}, [%2];" \
        : "=r"((r)[0]), "=r"((r)[1]) : "r"(addr))
#define CP16(dst, src) \
    asm volatile("cp.async.cg.shared.global [%0], [%1], 16;" :: "r"(dst), "l"(src))

// ---------------- LayerNorm -> fp16 ----------------
__global__ void ln_kernel(const float* __restrict__ x,
                          const float* __restrict__ g,
                          const float* __restrict__ b,
                          f16* __restrict__ oh) {
    const int row = blockIdx.x;
    const float* xr = x + (TLL)row * CC;
    float v[4]; float s = 0.f, ss = 0.f;
#pragma unroll
    for (int i = 0; i < 4; i++) {
        v[i] = xr[threadIdx.x + 256 * i];
        s += v[i]; ss += v[i] * v[i];
    }
#pragma unroll
    for (int o = 16; o; o >>= 1) {
        s  += __shfl_xor_sync(0xffffffffu, s, o);
        ss += __shfl_xor_sync(0xffffffffu, ss, o);
    }
    __shared__ float sh0[8], sh1[8];
    int w = threadIdx.x >> 5, l = threadIdx.x & 31;
    if (!l) { sh0[w] = s; sh1[w] = ss; }
    __syncthreads();
    if (threadIdx.x == 0) {
        float S = 0.f, SS = 0.f;
#pragma unroll
        for (int i = 0; i < 8; i++) { S += sh0[i]; SS += sh1[i]; }
        float mu = S * (1.0f / CC);
        float var = SS * (1.0f / CC) - mu * mu;
        sh0[0] = mu; sh1[0] = rsqrtf(var + 1e-5f);
    }
    __syncthreads();
    float mu = sh0[0], rstd = sh1[0];
#pragma unroll
    for (int i = 0; i < 4; i++) {
        int c = threadIdx.x + 256 * i;
        float o = (v[i] - mu) * rstd * g[c] + b[c];
        oh[(TLL)row * CC + c] = __float2half_rn(o);
    }
}

// ---------------- transpose fp32 -> fp16 hi ([K,N] -> [N,K]) ---------------
__global__ void transpose_conv(const float* __restrict__ in,
                               f16* __restrict__ oh, int ldin, int ldout) {
    __shared__ float t[32][33];
    int k0 = blockIdx.y * 32, n0 = blockIdx.x * 32;
    int tx = threadIdx.x, ty = threadIdx.y;
#pragma unroll
    for (int i = 0; i < 32; i += 8)
        t[ty + i][tx] = in[(TLL)(k0 + ty + i) * ldin + (n0 + tx)];
    __syncthreads();
#pragma unroll
    for (int i = 0; i < 32; i += 8)
        oh[(TLL)(n0 + ty + i) * ldout + (k0 + tx)] = __float2half_rn(t[tx][ty + i]);
}

// ---------------- fused flash attention -----------------------------------
// grid (16, 1, 64): z = b*16 + h, x = 128-row Q block. 256 threads, 8 warps,
// each warp owns 16 Q rows. K/V tiles 128x64, double buffered. y out: f16 hi.
__global__ void __launch_bounds__(256)
flash_attn(const f16* __restrict__ qkv, f16* __restrict__ yh) {
    constexpr int RS = 72;                     // f16 per smem row
    constexpr int TILE = 128 * RS * 2;         // bytes per 128x64 tile
    extern __shared__ __align__(16) f16 fsm[];
    const uint32_t sQ  = smem_u32(fsm);
    const uint32_t sKV = sQ + TILE;

    const int tid = threadIdx.x, lane = tid & 31, wid = tid >> 5;
    const int lq = lane >> 2, lr = lane & 3;
    const int z = blockIdx.z, bz = z >> 4, hz = z & 15;
    const int t0 = blockIdx.x * 128;

    const f16* Qg = qkv + ((TLL)bz * TT + t0) * (3 * CC) + hz * HD;
    const f16* Kg = qkv + ((TLL)bz * TT) * (3 * CC) + CC + hz * HD;
    const f16* Vg = Kg + CC;

#pragma unroll
    for (int t = 0; t < 4; t++) {
        int idx = tid + (t << 8);
        int r = idx >> 3, c = idx & 7;
        CP16(sQ + (r * RS + c * 8) * 2, Qg + (TLL)r * (3 * CC) + c * 8);
    }
    asm volatile("cp.async.commit_group;");

    auto stageKV = [&](int buf, int s0) {
        uint32_t base = sKV + buf * (2 * TILE);
#pragma unroll
        for (int t = 0; t < 4; t++) {
            int idx = tid + (t << 8);
            int r = idx >> 3, c = idx & 7;
            CP16(base + (r * RS + c * 8) * 2, Kg + (TLL)(s0 + r) * (3 * CC) + c * 8);
            CP16(base + TILE + (r * RS + c * 8) * 2, Vg + (TLL)(s0 + r) * (3 * CC) + c * 8);
        }
        asm volatile("cp.async.commit_group;");
    };
    stageKV(0, 0);

    uint32_t qf[4][4];
    float y[8][4];
    float m_lo = -1e30f, m_hi = -1e30f, l_lo = 0.f, l_hi = 0.f;
#pragma unroll
    for (int i = 0; i < 8; i++)
#pragma unroll
        for (int q = 0; q < 4; q++) y[i][q] = 0.f;

    const float c_s = 0.125f * 1.4426950408889634f;

    for (int it = 0; it < TT / 128; ++it) {
        if (it + 1 < TT / 128) {
            stageKV((it + 1) & 1, (it + 1) * 128);
            asm volatile("cp.async.wait_group 1;" ::: "memory");
        } else {
            asm volatile("cp.async.wait_group 0;" ::: "memory");
        }
        __syncthreads();

        if (it == 0) {
#pragma unroll
            for (int c = 0; c < 4; c++) {
                uint32_t a = sQ + (((wid * 16) + (lane & 15)) * RS
                                   + c * 16 + ((lane >> 4) & 1) * 8) * 2;
                LDSM4(qf[c], a);
            }
        }

        const uint32_t bbK = sKV + (it & 1) * (2 * TILE);
        const uint32_t bbV = bbK + TILE;

        float S[16][4];
#pragma unroll
        for (int nt = 0; nt < 16; nt++) {
            S[nt][0] = S[nt][1] = S[nt][2] = S[nt][3] = 0.f;
            uint32_t b0[4], b1[4];
            uint32_t a0 = bbK + ((nt * 8 + (lane & 7)) * RS + ((lane >> 3) & 3) * 8) * 2;
            LDSM4(b0, a0);
            LDSM4(b1, a0 + 64);
            mma_f16(S[nt], qf[0], b0);
            mma_f16(S[nt], qf[1], b0 + 2);
            mma_f16(S[nt], qf[2], b1);
            mma_f16(S[nt], qf[3], b1 + 2);
        }

        float mx0 = -1e30f, mx1 = -1e30f;
#pragma unroll
        for (int nt = 0; nt < 16; nt++) {
            S[nt][0] *= c_s; S[nt][1] *= c_s; S[nt][2] *= c_s; S[nt][3] *= c_s;
            mx0 = fmaxf(mx0, fmaxf(S[nt][0], S[nt][1]));
            mx1 = fmaxf(mx1, fmaxf(S[nt][2], S[nt][3]));
        }
        mx0 = fmaxf(mx0, __shfl_xor_sync(0xffffffffu, mx0, 1));
        mx0 = fmaxf(mx0, __shfl_xor_sync(0xffffffffu, mx0, 2));
        mx1 = fmaxf(mx1, __shfl_xor_sync(0xffffffffu, mx1, 1));
        mx1 = fmaxf(mx1, __shfl_xor_sync(0xffffffffu, mx1, 2));
        float nmlo = fmaxf(m_lo, mx0), nmhi = fmaxf(m_hi, mx1);
        float al = ex2f(m_lo - nmlo), ah = ex2f(m_hi - nmhi);
        m_lo = nmlo; m_hi = nmhi;
        l_lo *= al; l_hi *= ah;
#pragma unroll
        for (int i = 0; i < 8; i++) {
            y[i][0] *= al; y[i][1] *= al; y[i][2] *= ah; y[i][3] *= ah;
        }

        uint32_t pa[8][4];
#pragma unroll
        for (int kc = 0; kc < 8; kc++) {
#pragma unroll
            for (int half = 0; half < 2; half++) {
                int nt = 2 * kc + half;
                float p0 = ex2f(S[nt][0] - m_lo);
                float p1 = ex2f(S[nt][1] - m_lo);
                float p2 = ex2f(S[nt][2] - m_hi);
                float p3 = ex2f(S[nt][3] - m_hi);
                l_lo += p0 + p1; l_hi += p2 + p3;
                __half2 q01 = __floats2half2_rn(p0, p1);
                __half2 q23 = __floats2half2_rn(p2, p3);
                pa[kc][2 * half + 0] = *(uint32_t*)&q01;
                pa[kc][2 * half + 1] = *(uint32_t*)&q23;
            }
        }

#pragma unroll
        for (int kc = 0; kc < 8; kc++) {
#pragma unroll
            for (int np = 0; np < 4; np++) {
                uint32_t vf[4];
                uint32_t a = bbV + ((kc * 16 + ((lane >> 3) & 1) * 8 + (lane & 7)) * RS
                                    + np * 16 + ((lane >> 4) & 1) * 8) * 2;
                LDSM4T(vf, a);
                mma_f16(y[2 * np], pa[kc], vf);
                mma_f16(y[2 * np + 1], pa[kc], vf + 2);
            }
        }
        __syncthreads();
    }

    l_lo += __shfl_xor_sync(0xffffffffu, l_lo, 1);
    l_lo += __shfl_xor_sync(0xffffffffu, l_lo, 2);
    l_hi += __shfl_xor_sync(0xffffffffu, l_hi, 1);
    l_hi += __shfl_xor_sync(0xffffffffu, l_hi, 2);
    float inv_lo = 1.f / l_lo, inv_hi = 1.f / l_hi;

    TLL row_lo = (TLL)bz * TT + t0 + wid * 16 + lq;
    TLL row_hi = row_lo + 8;
#pragma unroll
    for (int nt = 0; nt < 8; nt++) {
        int col = hz * HD + nt * 8 + 2 * lr;
        __half2 p0 = __floats2half2_rn(y[nt][0] * inv_lo, y[nt][1] * inv_lo);
        __half2 p1 = __floats2half2_rn(y[nt][2] * inv_hi, y[nt][3] * inv_hi);
        *(__half2*)(yh + row_lo * CC + col) = p0;
        *(__half2*)(yh + row_hi * CC + col) = p1;
    }
}

// ---------------- fp16 mma.sync GEMM (plain, R10 shape) --------------------
// D[m][n] = scale * sum_k A[m][k]*B[n][k], K-major operands.
// Tile 128 x 128, BK=32, 256 threads, warp grid 2(m) x 4(n), double buffered.
// flags: 1=+bias, 2=gelu, 4=+residual(fp32), 16=f16 out (else fp32 out)
__global__ void __launch_bounds__(256)
hf_gemm(const f16* __restrict__ Ah, const f16* __restrict__ Bh,
        const float* __restrict__ bias, const float* __restrict__ res,
        float* __restrict__ Cf, f16* __restrict__ Oh,
        int K, TLL lda, TLL ldb, TLL ldc,
        float scale, int flags) {
    constexpr int BN = 128;
    constexpr int RS = 40;
    constexpr int A_ELEMS = 128 * RS;
    constexpr int B_ELEMS = BN * RS;
    constexpr int BUF = A_ELEMS + B_ELEMS;
    constexpr int WTN = BN / 4;
    constexpr int NI  = WTN / 8;

    extern __shared__ __align__(16) f16 dynsm[];
    const uint32_t sb = smem_u32(dynsm);

    const int tid = threadIdx.x, lane = tid & 31, wid = tid >> 5;
    const int wm = wid & 1, wn = wid >> 1;

    const TLL rowBase = (TLL)blockIdx.y * 128;
    const TLL colBase = (TLL)blockIdx.x * BN;

    float acc[4][NI][4];
#pragma unroll
    for (int i = 0; i < 4; i++)
#pragma unroll
        for (int j = 0; j < NI; j++)
#pragma unroll
            for (int q = 0; q < 4; q++) acc[i][j][q] = 0.f;

    auto stage = [&](int buf, int k0) {
        const uint32_t bb = sb + buf * (BUF * 2);
#pragma unroll
        for (int t = 0; t < 2; t++) {               // A: 512 chunks of 16B
            int idx = tid + (t << 8);
            int r = idx >> 2, c = idx & 3;
            const f16* g = Ah + (rowBase + r) * lda + (k0 + c * 8);
            uint32_t d = bb + (r * RS + c * 8) * 2;
            CP16(d, g);
        }
#pragma unroll
        for (int t = 0; t < 2; t++) {               // B: 512 chunks
            int idx = tid + (t << 8);
            int r = idx >> 2, c = idx & 3;
            const f16* g = Bh + (colBase + r) * ldb + (k0 + c * 8);
            uint32_t d = bb + (A_ELEMS + r * RS + c * 8) * 2;
            CP16(d, g);
        }
        asm volatile("cp.async.commit_group;");
    };

    const int iters = K / 32;
    int buf = 0;
    stage(0, 0);

    for (int it = 0; it < iters; ++it) {
        if (it + 1 < iters) {
            stage(buf ^ 1, (it + 1) * 32);
            asm volatile("cp.async.wait_group 1;" ::: "memory");
        } else {
            asm volatile("cp.async.wait_group 0;" ::: "memory");
        }
        __syncthreads();

        const uint32_t bb = sb + buf * (BUF * 2);
        const uint32_t aRow = (wm * 64 + (lane & 15)) * (RS * 2) + ((lane >> 4) << 4);
        const uint32_t bRow = (wn * WTN + (lane & 7)) * (RS * 2) + (((lane >> 3) & 1) << 4);

#pragma unroll
        for (int ks = 0; ks < 2; ks++) {
            uint32_t bh[NI][2];
#pragma unroll
            for (int ni = 0; ni < NI; ni++) {
                uint32_t ba = bb + A_ELEMS * 2 + bRow + ni * (8 * RS * 2) + ks * 32;
                LDSM2(bh[ni], ba);
            }
#pragma unroll
            for (int mi = 0; mi < 4; mi++) {
                uint32_t aa = bb + aRow + mi * (16 * RS * 2) + ks * 32;
                uint32_t ah[4];
                LDSM4(ah, aa);
#pragma unroll
                for (int ni = 0; ni < NI; ni++)
                    mma_f16(acc[mi][ni], ah, bh[ni]);
            }
        }
        __syncthreads();
        buf ^= 1;
    }

    const int lq = lane >> 2, lr = lane & 3;
#pragma unroll
    for (int mi = 0; mi < 4; mi++) {
        TLL r0 = rowBase + wm * 64 + mi * 16 + lq;
#pragma unroll
        for (int ni = 0; ni < NI; ni++) {
            TLL c = colBase + wn * WTN + ni * 8 + 2 * lr;
            float v00 = acc[mi][ni][0] * scale, v01 = acc[mi][ni][1] * scale;
            float v10 = acc[mi][ni][2] * scale, v11 = acc[mi][ni][3] * scale;
            if (flags & 1) {
                float b0 = bias[c], b1 = bias[c + 1];
                v00 += b0; v01 += b1; v10 += b0; v11 += b1;
            }
            if (flags & 2) {
                v00 = gelu_f(v00); v01 = gelu_f(v01);
                v10 = gelu_f(v10); v11 = gelu_f(v11);
            }
            if (flags & 4) {
                float2 ra = *(const float2*)(res + r0 * ldc + c);
                float2 rb = *(const float2*)(res + (r0 + 8) * ldc + c);
                v00 += ra.x; v01 += ra.y; v10 += rb.x; v11 += rb.y;
            }
            if (flags & 16) {
                *(__half2*)(Oh + r0 * ldc + c) = __floats2half2_rn(v00, v01);
                *(__half2*)(Oh + (r0 + 8) * ldc + c) = __floats2half2_rn(v10, v11);
            } else {
                *(float2*)(Cf + r0 * ldc + c) = make_float2(v00, v01);
                *(float2*)(Cf + (r0 + 8) * ldc + c) = make_float2(v10, v11);
            }
        }
    }
}

// ---------------- launch ----------------
extern "C" void kernel_launch(void* const* d_in, const int* in_sizes, int n_in,
                              void* d_out, int out_size) {
    const float* x          = (const float*)d_in[0];
    const float* ln1_g      = (const float*)d_in[1];
    const float* ln1_b      = (const float*)d_in[2];
    const float* w_qkv      = (const float*)d_in[3];
    const float* b_qkv      = (const float*)d_in[4];
    const float* w_attnproj = (const float*)d_in[5];
    const float* b_attnproj = (const float*)d_in[6];
    const float* ln2_g      = (const float*)d_in[7];
    const float* ln2_b      = (const float*)d_in[8];
    const float* w_fc       = (const float*)d_in[9];
    const float* b_fc       = (const float*)d_in[10];
    const float* w_proj     = (const float*)d_in[11];
    const float* b_proj     = (const float*)d_in[12];
    float* out = (float*)d_out;

    float *x1;
    f16 *h_hi, *qkv_hi, *y_hi, *h2_hi, *ff_hi;
    f16 *wqkvT_hi, *wapT_hi, *wfcT_hi, *wprjT_hi;
    cudaGetSymbolAddress((void**)&x1,   g_x1);
    cudaGetSymbolAddress((void**)&h_hi, g_h_hi);
    cudaGetSymbolAddress((void**)&qkv_hi, g_qkv_hi);
    cudaGetSymbolAddress((void**)&y_hi, g_y_hi);
    cudaGetSymbolAddress((void**)&h2_hi, g_h2_hi);
    cudaGetSymbolAddress((void**)&ff_hi, g_ff_hi);
    cudaGetSymbolAddress((void**)&wqkvT_hi, g_wqkvT_hi);
    cudaGetSymbolAddress((void**)&wapT_hi, g_wapT_hi);
    cudaGetSymbolAddress((void**)&wfcT_hi, g_wfcT_hi);
    cudaGetSymbolAddress((void**)&wprjT_hi, g_wprjT_hi);

    static bool attr_done = false;
    if (!attr_done) {
        cudaFuncSetAttribute(hf_gemm,    cudaFuncAttributeMaxDynamicSharedMemorySize, 40960);
        cudaFuncSetAttribute(flash_attn, cudaFuncAttributeMaxDynamicSharedMemorySize, 92160);
        attr_done = true;
    }
    const int SM1 = 40960, SMFA = 92160;

    dim3 tb(32, 8);
    transpose_conv<<<dim3(3 * CC / 32, CC / 32), tb>>>(w_qkv, wqkvT_hi, 3 * CC, CC);
    transpose_conv<<<dim3(CC / 32, CC / 32), tb>>>(w_attnproj, wapT_hi, CC, CC);
    transpose_conv<<<dim3(DFF / 32, CC / 32), tb>>>(w_fc, wfcT_hi, DFF, CC);
    transpose_conv<<<dim3(CC / 32, DFF / 32), tb>>>(w_proj, wprjT_hi, CC, DFF);

    // 1) h = LN1(x)
    ln_kernel<<<ROWS, 256>>>(x, ln1_g, ln1_b, h_hi);

    // 2) qkv = h @ w_qkv + b_qkv  (f16 out)
    hf_gemm<<<dim3(3 * CC / 128, ROWS / 128, 1), 256, SM1>>>(
        h_hi, wqkvT_hi, b_qkv, nullptr,
        nullptr, qkv_hi, CC,
        CC, CC, 3 * CC, 1.0f, 1 | 16);

    // 3-6) fused attention: y = softmax(QK^T/8) V  (f16 out)
    flash_attn<<<dim3(TT / 128, 1, BB * HH), 256, SMFA>>>(qkv_hi, y_hi);

    // 7) x1 = x + y @ w_attnproj + b  (fp32 out)
    hf_gemm<<<dim3(CC / 128, ROWS / 128, 1), 256, SM1>>>(
        y_hi, wapT_hi, b_attnproj, x,
        x1, nullptr, CC,
        CC, CC, CC, 1.0f, 1 | 4);

    // 8) h2 = LN2(x1)
    ln_kernel<<<ROWS, 256>>>(x1, ln2_g, ln2_b, h2_hi);

    // 9) ff = gelu(h2 @ w_fc + b_fc)  (f16 out)
    hf_gemm<<<dim3(DFF / 128, ROWS / 128, 1), 256, SM1>>>(
        h2_hi, wfcT_hi, b_fc, nullptr,
        nullptr, ff_hi, CC,
        CC, CC, DFF, 1.0f, 1 | 2 | 16);

    // 10) out = x1 + ff @ w_proj + b_proj  (fp32 out)
    hf_gemm<<<dim3(CC / 128, ROWS / 128, 1), 256, SM1>>>(
        ff_hi, wprjT_hi, b_proj, x1,
        out, nullptr, DFF,
        DFF, DFF, CC, 1.0f, 1 | 4);
}

// round 13
// speedup vs baseline: 1.3760x; 1.0074x over previous
#include <cuda_runtime.h>
#include <cuda_fp16.h>
#include <math.h>
#include <stdint.h>

typedef long long TLL;
typedef __half f16;

// ---------------- problem constants ----------------
#define BB   4
#define TT   2048
#define CC   1024
#define HH   16
#define HD   64
#define DFF  4096
#define ROWS (BB*TT)          // 8192

// ---------------- scratch ----------------
__device__ float g_x1  [(TLL)ROWS*CC];          // residual 1 (fp32)

__device__ f16 g_h_hi [(TLL)ROWS*CC];
__device__ f16 g_qkv_hi[(TLL)ROWS*3*CC];
__device__ f16 g_y_hi [(TLL)ROWS*CC];
__device__ f16 g_h2_hi[(TLL)ROWS*CC];
__device__ f16 g_ff_hi[(TLL)ROWS*DFF];
__device__ f16 g_wqkvT_hi[(TLL)3*CC*CC];
__device__ f16 g_wapT_hi [(TLL)CC*CC];
__device__ f16 g_wfcT_hi [(TLL)DFF*CC];
__device__ f16 g_wprjT_hi[(TLL)CC*DFF];

// ---------------- helpers ----------------
__device__ __forceinline__ uint32_t smem_u32(const void* p) {
    return (uint32_t)__cvta_generic_to_shared(p);
}
__device__ __forceinline__ float tanh_ap(float x) {
    float y; asm("tanh.approx.f32 %0, %1;" : "=f"(y) : "f"(x)); return y;
}
__device__ __forceinline__ float gelu_f(float x) {
    const float c = 0.7978845608028654f;
    float t = tanh_ap(c * (x + 0.044715f * x * x * x));
    return 0.5f * x * (1.0f + t);
}
__device__ __forceinline__ float ex2f(float x) {
    float y; asm("ex2.approx.f32 %0, %1;" : "=f"(y) : "f"(x)); return y;
}
__device__ __forceinline__ void mma_f16(float* d, const uint32_t* a, const uint32_t* b) {
    asm volatile(
        "mma.sync.aligned.m16n8k16.row.col.f32.f16.f16.f32 "
        "{%0,%1,%2,%3}, {%4,%5,%6,%7}, {%8,%9}, {%0,%1,%2,%3};"
        : "+f"(d[0]), "+f"(d[1]), "+f"(d[2]), "+f"(d[3])
        : "r"(a[0]), "r"(a[1]), "r"(a[2]), "r"(a[3]), "r"(b[0]), "r"(b[1]));
}
#define LDSM4(r, addr) \
    asm volatile("ldmatrix.sync.aligned.m8n8.x4.shared.b16 {%0,%1,%2,%3}, [%4];" \
        : "=r"((r)[0]), "=r"((r)[1]), "=r"((r)[2]), "=r"((r)[3]) : "r"(addr))
#define LDSM4T(r, addr) \
    asm volatile("ldmatrix.sync.aligned.m8n8.x4.trans.shared.b16 {%0,%1,%2,%3}, [%4];" \
        : "=r"((r)[0]), "=r"((r)[1]), "=r"((r)[2]), "=r"((r)[3]) : "r"(addr))
#define LDSM2(r, addr) \
    asm volatile("ldmatrix.sync.aligned.m8n8.x2.shared.b16 {%0,%1}, [%2];" \
        : "=r"((r)[0]), "=r"((r)[1]) : "r"(addr))
#define CP16(dst, src) \
    asm volatile("cp.async.cg.shared.global [%0], [%1], 16;" :: "r"(dst), "l"(src))

// ---------------- LayerNorm -> fp16 ----------------
__global__ void ln_kernel(const float* __restrict__ x,
                          const float* __restrict__ g,
                          const float* __restrict__ b,
                          f16* __restrict__ oh) {
    const int row = blockIdx.x;
    const float* xr = x + (TLL)row * CC;
    float v[4]; float s = 0.f, ss = 0.f;
#pragma unroll
    for (int i = 0; i < 4; i++) {
        v[i] = xr[threadIdx.x + 256 * i];
        s += v[i]; ss += v[i] * v[i];
    }
#pragma unroll
    for (int o = 16; o; o >>= 1) {
        s  += __shfl_xor_sync(0xffffffffu, s, o);
        ss += __shfl_xor_sync(0xffffffffu, ss, o);
    }
    __shared__ float sh0[8], sh1[8];
    int w = threadIdx.x >> 5, l = threadIdx.x & 31;
    if (!l) { sh0[w] = s; sh1[w] = ss; }
    __syncthreads();
    if (threadIdx.x == 0) {
        float S = 0.f, SS = 0.f;
#pragma unroll
        for (int i = 0; i < 8; i++) { S += sh0[i]; SS += sh1[i]; }
        float mu = S * (1.0f / CC);
        float var = SS * (1.0f / CC) - mu * mu;
        sh0[0] = mu; sh1[0] = rsqrtf(var + 1e-5f);
    }
    __syncthreads();
    float mu = sh0[0], rstd = sh1[0];
#pragma unroll
    for (int i = 0; i < 4; i++) {
        int c = threadIdx.x + 256 * i;
        float o = (v[i] - mu) * rstd * g[c] + b[c];
        oh[(TLL)row * CC + c] = __float2half_rn(o);
    }
}

// ---------------- transpose fp32 -> fp16 hi ([K,N] -> [N,K]) ---------------
__global__ void transpose_conv(const float* __restrict__ in,
                               f16* __restrict__ oh, int ldin, int ldout) {
    __shared__ float t[32][33];
    int k0 = blockIdx.y * 32, n0 = blockIdx.x * 32;
    int tx = threadIdx.x, ty = threadIdx.y;
#pragma unroll
    for (int i = 0; i < 32; i += 8)
        t[ty + i][tx] = in[(TLL)(k0 + ty + i) * ldin + (n0 + tx)];
    __syncthreads();
#pragma unroll
    for (int i = 0; i < 32; i += 8)
        oh[(TLL)(n0 + ty + i) * ldout + (k0 + tx)] = __float2half_rn(t[tx][ty + i]);
}

// ---------------- fused flash attention -----------------------------------
// grid (16, 1, 64): z = b*16 + h, x = 128-row Q block. 256 threads, 8 warps,
// each warp owns 16 Q rows. K/V tiles 128x64, double buffered. y out: f16 hi.
__global__ void __launch_bounds__(256)
flash_attn(const f16* __restrict__ qkv, f16* __restrict__ yh) {
    constexpr int RS = 72;                     // f16 per smem row
    constexpr int TILE = 128 * RS * 2;         // bytes per 128x64 tile
    extern __shared__ __align__(16) f16 fsm[];
    const uint32_t sQ  = smem_u32(fsm);
    const uint32_t sKV = sQ + TILE;

    const int tid = threadIdx.x, lane = tid & 31, wid = tid >> 5;
    const int lq = lane >> 2, lr = lane & 3;
    const int z = blockIdx.z, bz = z >> 4, hz = z & 15;
    const int t0 = blockIdx.x * 128;

    const f16* Qg = qkv + ((TLL)bz * TT + t0) * (3 * CC) + hz * HD;
    const f16* Kg = qkv + ((TLL)bz * TT) * (3 * CC) + CC + hz * HD;
    const f16* Vg = Kg + CC;

#pragma unroll
    for (int t = 0; t < 4; t++) {
        int idx = tid + (t << 8);
        int r = idx >> 3, c = idx & 7;
        CP16(sQ + (r * RS + c * 8) * 2, Qg + (TLL)r * (3 * CC) + c * 8);
    }
    asm volatile("cp.async.commit_group;");

    auto stageKV = [&](int buf, int s0) {
        uint32_t base = sKV + buf * (2 * TILE);
#pragma unroll
        for (int t = 0; t < 4; t++) {
            int idx = tid + (t << 8);
            int r = idx >> 3, c = idx & 7;
            CP16(base + (r * RS + c * 8) * 2, Kg + (TLL)(s0 + r) * (3 * CC) + c * 8);
            CP16(base + TILE + (r * RS + c * 8) * 2, Vg + (TLL)(s0 + r) * (3 * CC) + c * 8);
        }
        asm volatile("cp.async.commit_group;");
    };
    stageKV(0, 0);

    uint32_t qf[4][4];
    float y[8][4];
    float m_lo = -1e30f, m_hi = -1e30f, l_lo = 0.f, l_hi = 0.f;
#pragma unroll
    for (int i = 0; i < 8; i++)
#pragma unroll
        for (int q = 0; q < 4; q++) y[i][q] = 0.f;

    const float c_s = 0.125f * 1.4426950408889634f;

    for (int it = 0; it < TT / 128; ++it) {
        if (it + 1 < TT / 128) {
            stageKV((it + 1) & 1, (it + 1) * 128);
            asm volatile("cp.async.wait_group 1;" ::: "memory");
        } else {
            asm volatile("cp.async.wait_group 0;" ::: "memory");
        }
        __syncthreads();

        if (it == 0) {
#pragma unroll
            for (int c = 0; c < 4; c++) {
                uint32_t a = sQ + (((wid * 16) + (lane & 15)) * RS
                                   + c * 16 + ((lane >> 4) & 1) * 8) * 2;
                LDSM4(qf[c], a);
            }
        }

        const uint32_t bbK = sKV + (it & 1) * (2 * TILE);
        const uint32_t bbV = bbK + TILE;

        float S[16][4];
#pragma unroll
        for (int nt = 0; nt < 16; nt++) {
            S[nt][0] = S[nt][1] = S[nt][2] = S[nt][3] = 0.f;
            uint32_t b0[4], b1[4];
            uint32_t a0 = bbK + ((nt * 8 + (lane & 7)) * RS + ((lane >> 3) & 3) * 8) * 2;
            LDSM4(b0, a0);
            LDSM4(b1, a0 + 64);
            mma_f16(S[nt], qf[0], b0);
            mma_f16(S[nt], qf[1], b0 + 2);
            mma_f16(S[nt], qf[2], b1);
            mma_f16(S[nt], qf[3], b1 + 2);
        }

        float mx0 = -1e30f, mx1 = -1e30f;
#pragma unroll
        for (int nt = 0; nt < 16; nt++) {
            S[nt][0] *= c_s; S[nt][1] *= c_s; S[nt][2] *= c_s; S[nt][3] *= c_s;
            mx0 = fmaxf(mx0, fmaxf(S[nt][0], S[nt][1]));
            mx1 = fmaxf(mx1, fmaxf(S[nt][2], S[nt][3]));
        }
        mx0 = fmaxf(mx0, __shfl_xor_sync(0xffffffffu, mx0, 1));
        mx0 = fmaxf(mx0, __shfl_xor_sync(0xffffffffu, mx0, 2));
        mx1 = fmaxf(mx1, __shfl_xor_sync(0xffffffffu, mx1, 1));
        mx1 = fmaxf(mx1, __shfl_xor_sync(0xffffffffu, mx1, 2));
        float nmlo = fmaxf(m_lo, mx0), nmhi = fmaxf(m_hi, mx1);
        float al = ex2f(m_lo - nmlo), ah = ex2f(m_hi - nmhi);
        m_lo = nmlo; m_hi = nmhi;
        l_lo *= al; l_hi *= ah;
#pragma unroll
        for (int i = 0; i < 8; i++) {
            y[i][0] *= al; y[i][1] *= al; y[i][2] *= ah; y[i][3] *= ah;
        }

        uint32_t pa[8][4];
#pragma unroll
        for (int kc = 0; kc < 8; kc++) {
#pragma unroll
            for (int half = 0; half < 2; half++) {
                int nt = 2 * kc + half;
                float p0 = ex2f(S[nt][0] - m_lo);
                float p1 = ex2f(S[nt][1] - m_lo);
                float p2 = ex2f(S[nt][2] - m_hi);
                float p3 = ex2f(S[nt][3] - m_hi);
                l_lo += p0 + p1; l_hi += p2 + p3;
                __half2 q01 = __floats2half2_rn(p0, p1);
                __half2 q23 = __floats2half2_rn(p2, p3);
                pa[kc][2 * half + 0] = *(uint32_t*)&q01;
                pa[kc][2 * half + 1] = *(uint32_t*)&q23;
            }
        }

#pragma unroll
        for (int kc = 0; kc < 8; kc++) {
#pragma unroll
            for (int np = 0; np < 4; np++) {
                uint32_t vf[4];
                uint32_t a = bbV + ((kc * 16 + ((lane >> 3) & 1) * 8 + (lane & 7)) * RS
                                    + np * 16 + ((lane >> 4) & 1) * 8) * 2;
                LDSM4T(vf, a);
                mma_f16(y[2 * np], pa[kc], vf);
                mma_f16(y[2 * np + 1], pa[kc], vf + 2);
            }
        }
        __syncthreads();
    }

    l_lo += __shfl_xor_sync(0xffffffffu, l_lo, 1);
    l_lo += __shfl_xor_sync(0xffffffffu, l_lo, 2);
    l_hi += __shfl_xor_sync(0xffffffffu, l_hi, 1);
    l_hi += __shfl_xor_sync(0xffffffffu, l_hi, 2);
    float inv_lo = 1.f / l_lo, inv_hi = 1.f / l_hi;

    TLL row_lo = (TLL)bz * TT + t0 + wid * 16 + lq;
    TLL row_hi = row_lo + 8;
#pragma unroll
    for (int nt = 0; nt < 8; nt++) {
        int col = hz * HD + nt * 8 + 2 * lr;
        __half2 p0 = __floats2half2_rn(y[nt][0] * inv_lo, y[nt][1] * inv_lo);
        __half2 p1 = __floats2half2_rn(y[nt][2] * inv_hi, y[nt][3] * inv_hi);
        *(__half2*)(yh + row_lo * CC + col) = p0;
        *(__half2*)(yh + row_hi * CC + col) = p1;
    }
}

// ---------------- fp16 mma.sync GEMM, 128x128, 3-stage single-sync ---------
// D[m][n] = scale * sum_k A[m][k]*B[n][k], K-major operands.
// Tile 128 x 128, BK=32, 256 threads, warp grid 2(m) x 4(n).
// 3-stage cp.async ring, ONE __syncthreads per iteration; 2 CTA/SM.
// flags: 1=+bias, 2=gelu, 4=+residual(fp32), 16=f16 out (else fp32 out)
__global__ void __launch_bounds__(256)
hf_gemm(const f16* __restrict__ Ah, const f16* __restrict__ Bh,
        const float* __restrict__ bias, const float* __restrict__ res,
        float* __restrict__ Cf, f16* __restrict__ Oh,
        int K, TLL lda, TLL ldb, TLL ldc,
        float scale, int flags) {
    constexpr int BN = 128;
    constexpr int RS = 40;
    constexpr int A_ELEMS = 128 * RS;
    constexpr int B_ELEMS = BN * RS;
    constexpr int BUF = A_ELEMS + B_ELEMS;
    constexpr int WTN = BN / 4;
    constexpr int NI  = WTN / 8;

    extern __shared__ __align__(16) f16 dynsm[];
    const uint32_t sb = smem_u32(dynsm);

    const int tid = threadIdx.x, lane = tid & 31, wid = tid >> 5;
    const int wm = wid & 1, wn = wid >> 1;

    const TLL rowBase = (TLL)blockIdx.y * 128;
    const TLL colBase = (TLL)blockIdx.x * BN;

    float acc[4][NI][4];
#pragma unroll
    for (int i = 0; i < 4; i++)
#pragma unroll
        for (int j = 0; j < NI; j++)
#pragma unroll
            for (int q = 0; q < 4; q++) acc[i][j][q] = 0.f;

    auto stage = [&](int s, int k0) {
        const uint32_t bb = sb + (s % 3) * (BUF * 2);
#pragma unroll
        for (int t = 0; t < 2; t++) {               // A: 512 chunks of 16B
            int idx = tid + (t << 8);
            int r = idx >> 2, c = idx & 3;
            const f16* g = Ah + (rowBase + r) * lda + (k0 + c * 8);
            uint32_t d = bb + (r * RS + c * 8) * 2;
            CP16(d, g);
        }
#pragma unroll
        for (int t = 0; t < 2; t++) {               // B: 512 chunks
            int idx = tid + (t << 8);
            int r = idx >> 2, c = idx & 3;
            const f16* g = Bh + (colBase + r) * ldb + (k0 + c * 8);
            uint32_t d = bb + (A_ELEMS + r * RS + c * 8) * 2;
            CP16(d, g);
        }
        asm volatile("cp.async.commit_group;");
    };

    const int iters = K / 32;
    stage(0, 0);
    if (iters > 1) stage(1, 32);

    const uint32_t aRow = (wm * 64 + (lane & 15)) * (RS * 2) + ((lane >> 4) << 4);
    const uint32_t bRow = (wn * WTN + (lane & 7)) * (RS * 2) + (((lane >> 3) & 1) << 4);

    for (int it = 0; it < iters; ++it) {
        if (it + 1 < iters) {
            asm volatile("cp.async.wait_group 1;" ::: "memory");
        } else {
            asm volatile("cp.async.wait_group 0;" ::: "memory");
        }
        __syncthreads();
        // Buffer (it+2)%3 == (it-1)%3 was consumed before this barrier.
        if (it + 2 < iters) stage(it + 2, (it + 2) * 32);

        const uint32_t bb = sb + (it % 3) * (BUF * 2);

#pragma unroll
        for (int ks = 0; ks < 2; ks++) {
            uint32_t bh[NI][2];
#pragma unroll
            for (int ni = 0; ni < NI; ni++) {
                uint32_t ba = bb + A_ELEMS * 2 + bRow + ni * (8 * RS * 2) + ks * 32;
                LDSM2(bh[ni], ba);
            }
#pragma unroll
            for (int mi = 0; mi < 4; mi++) {
                uint32_t aa = bb + aRow + mi * (16 * RS * 2) + ks * 32;
                uint32_t ah[4];
                LDSM4(ah, aa);
#pragma unroll
                for (int ni = 0; ni < NI; ni++)
                    mma_f16(acc[mi][ni], ah, bh[ni]);
            }
        }
    }

    const int lq = lane >> 2, lr = lane & 3;
#pragma unroll
    for (int mi = 0; mi < 4; mi++) {
        TLL r0 = rowBase + wm * 64 + mi * 16 + lq;
#pragma unroll
        for (int ni = 0; ni < NI; ni++) {
            TLL c = colBase + wn * WTN + ni * 8 + 2 * lr;
            float v00 = acc[mi][ni][0] * scale, v01 = acc[mi][ni][1] * scale;
            float v10 = acc[mi][ni][2] * scale, v11 = acc[mi][ni][3] * scale;
            if (flags & 1) {
                float b0 = bias[c], b1 = bias[c + 1];
                v00 += b0; v01 += b1; v10 += b0; v11 += b1;
            }
            if (flags & 2) {
                v00 = gelu_f(v00); v01 = gelu_f(v01);
                v10 = gelu_f(v10); v11 = gelu_f(v11);
            }
            if (flags & 4) {
                float2 ra = *(const float2*)(res + r0 * ldc + c);
                float2 rb = *(const float2*)(res + (r0 + 8) * ldc + c);
                v00 += ra.x; v01 += ra.y; v10 += rb.x; v11 += rb.y;
            }
            if (flags & 16) {
                *(__half2*)(Oh + r0 * ldc + c) = __floats2half2_rn(v00, v01);
                *(__half2*)(Oh + (r0 + 8) * ldc + c) = __floats2half2_rn(v10, v11);
            } else {
                *(float2*)(Cf + r0 * ldc + c) = make_float2(v00, v01);
                *(float2*)(Cf + (r0 + 8) * ldc + c) = make_float2(v10, v11);
            }
        }
    }
}

// ---------------- launch ----------------
extern "C" void kernel_launch(void* const* d_in, const int* in_sizes, int n_in,
                              void* d_out, int out_size) {
    const float* x          = (const float*)d_in[0];
    const float* ln1_g      = (const float*)d_in[1];
    const float* ln1_b      = (const float*)d_in[2];
    const float* w_qkv      = (const float*)d_in[3];
    const float* b_qkv      = (const float*)d_in[4];
    const float* w_attnproj = (const float*)d_in[5];
    const float* b_attnproj = (const float*)d_in[6];
    const float* ln2_g      = (const float*)d_in[7];
    const float* ln2_b      = (const float*)d_in[8];
    const float* w_fc       = (const float*)d_in[9];
    const float* b_fc       = (const float*)d_in[10];
    const float* w_proj     = (const float*)d_in[11];
    const float* b_proj     = (const float*)d_in[12];
    float* out = (float*)d_out;

    float *x1;
    f16 *h_hi, *qkv_hi, *y_hi, *h2_hi, *ff_hi;
    f16 *wqkvT_hi, *wapT_hi, *wfcT_hi, *wprjT_hi;
    cudaGetSymbolAddress((void**)&x1,   g_x1);
    cudaGetSymbolAddress((void**)&h_hi, g_h_hi);
    cudaGetSymbolAddress((void**)&qkv_hi, g_qkv_hi);
    cudaGetSymbolAddress((void**)&y_hi, g_y_hi);
    cudaGetSymbolAddress((void**)&h2_hi, g_h2_hi);
    cudaGetSymbolAddress((void**)&ff_hi, g_ff_hi);
    cudaGetSymbolAddress((void**)&wqkvT_hi, g_wqkvT_hi);
    cudaGetSymbolAddress((void**)&wapT_hi, g_wapT_hi);
    cudaGetSymbolAddress((void**)&wfcT_hi, g_wfcT_hi);
    cudaGetSymbolAddress((void**)&wprjT_hi, g_wprjT_hi);

    static bool attr_done = false;
    if (!attr_done) {
        cudaFuncSetAttribute(hf_gemm,    cudaFuncAttributeMaxDynamicSharedMemorySize, 61440);
        cudaFuncSetAttribute(flash_attn, cudaFuncAttributeMaxDynamicSharedMemorySize, 92160);
        attr_done = true;
    }
    const int SM1 = 61440, SMFA = 92160;

    dim3 tb(32, 8);
    transpose_conv<<<dim3(3 * CC / 32, CC / 32), tb>>>(w_qkv, wqkvT_hi, 3 * CC, CC);
    transpose_conv<<<dim3(CC / 32, CC / 32), tb>>>(w_attnproj, wapT_hi, CC, CC);
    transpose_conv<<<dim3(DFF / 32, CC / 32), tb>>>(w_fc, wfcT_hi, DFF, CC);
    transpose_conv<<<dim3(CC / 32, DFF / 32), tb>>>(w_proj, wprjT_hi, CC, DFF);

    // 1) h = LN1(x)
    ln_kernel<<<ROWS, 256>>>(x, ln1_g, ln1_b, h_hi);

    // 2) qkv = h @ w_qkv + b_qkv  (f16 out)
    hf_gemm<<<dim3(3 * CC / 128, ROWS / 128, 1), 256, SM1>>>(
        h_hi, wqkvT_hi, b_qkv, nullptr,
        nullptr, qkv_hi, CC,
        CC, CC, 3 * CC, 1.0f, 1 | 16);

    // 3-6) fused attention: y = softmax(QK^T/8) V  (f16 out)
    flash_attn<<<dim3(TT / 128, 1, BB * HH), 256, SMFA>>>(qkv_hi, y_hi);

    // 7) x1 = x + y @ w_attnproj + b  (fp32 out)
    hf_gemm<<<dim3(CC / 128, ROWS / 128, 1), 256, SM1>>>(
        y_hi, wapT_hi, b_attnproj, x,
        x1, nullptr, CC,
        CC, CC, CC, 1.0f, 1 | 4);

    // 8) h2 = LN2(x1)
    ln_kernel<<<ROWS, 256>>>(x1, ln2_g, ln2_b, h2_hi);

    // 9) ff = gelu(h2 @ w_fc + b_fc)  (f16 out)
    hf_gemm<<<dim3(DFF / 128, ROWS / 128, 1), 256, SM1>>>(
        h2_hi, wfcT_hi, b_fc, nullptr,
        nullptr, ff_hi, CC,
        CC, CC, DFF, 1.0f, 1 | 2 | 16);

    // 10) out = x1 + ff @ w_proj + b_proj  (fp32 out)
    hf_gemm<<<dim3(CC / 128, ROWS / 128, 1), 256, SM1>>>(
        ff_hi, wprjT_hi, b_proj, x1,
        out, nullptr, DFF,
        DFF, DFF, CC, 1.0f, 1 | 4);
}